// round 13
// baseline (speedup 1.0000x reference)
#include <cuda_runtime.h>
#include <math.h>

#define NN 224
#define HW (NN*NN)
#define BATCH 32

typedef unsigned long long ull;

// d_out offsets (floats), in reference return order:
// h1n, c1n, h2n, c2n, h3n, c3n, reconstruction, fovea, hr, hidden
#define SZ8  ((size_t)BATCH*8*HW)
#define SZ16 ((size_t)BATCH*16*HW)
#define SZ3  ((size_t)BATCH*3*HW)
#define OFF_H1     ((size_t)0)
#define OFF_C1     (OFF_H1 + SZ8)
#define OFF_H2     (OFF_C1 + SZ8)
#define OFF_C2     (OFF_H2 + SZ16)
#define OFF_H3     (OFF_C2 + SZ16)
#define OFF_C3     (OFF_H3 + SZ3)
#define OFF_RECON  (OFF_C3 + SZ3)
#define OFF_FOVEA  (OFF_RECON + SZ3)
#define OFF_HR     (OFF_FOVEA + SZ3)
#define OFF_HIDDEN (OFF_HR + SZ3)

// HW tanh (sm_75+): single MUFU.TANH, max err ~1e-5 — far under 1e-3 budget
__device__ __forceinline__ float hw_tanh(float x) {
    float y;
    asm("tanh.approx.f32 %0, %1;" : "=f"(y) : "f"(x));
    return y;
}
// sigmoid via HW tanh: sigma(x) = 0.5 + 0.5*tanh(0.5x)  (3 instr)
__device__ __forceinline__ float fast_sig(float x) {
    return fmaf(hw_tanh(0.5f * x), 0.5f, 0.5f);
}

// ---- packed f32x2 helpers (sm_103a) --------------------------------------
__device__ __forceinline__ ull pack2(float lo, float hi) {
    ull r;
    asm("mov.b64 %0, {%1, %2};" : "=l"(r) : "f"(lo), "f"(hi));
    return r;
}
__device__ __forceinline__ void unpack2(ull v, float& lo, float& hi) {
    asm("mov.b64 {%0, %1}, %2;" : "=f"(lo), "=f"(hi) : "l"(v));
}
__device__ __forceinline__ ull fma2(ull a, ull b, ull c) {
    ull d;
    asm("fma.rn.f32x2 %0, %1, %2, %3;" : "=l"(d) : "l"(a), "l"(b), "l"(c));
    return d;
}

// ---------------------------------------------------------------------------
// Fused ConvLSTM step, f32x2 packed gate-pairs.
// TW x TH output tile, TW*TH/2 threads; thread handles col tx, 2 rows.
// smem: CIN halo tiles ((TH+2) x (TW+2)) + weights [ch][ci][tap][gate]
// so ONE LDS.128 per tap yields both packed (w_i,w_f) and (w_o,w_g).
// STAGE_W: stage only CHB channels of weights per outer iteration (conv2) —
// input halo is loaded ONCE per block.
// PIPE: explicit ping-pong double-buffer of the per-channel value loads —
// the 12 LDS for channel ci+1 issue before the FFMA2 block of channel ci,
// hiding LDS latency behind compute. Requires MINB=3 (85-reg) headroom.
// FUSE_MASK: layer-1 computes r_t0 = x*mask inline and emits fovea/hr.
// ---------------------------------------------------------------------------
template<int CX, int CH, int CHB, int TW, int TH, int MINB,
         bool FUSE_MASK, bool STAGE_W, bool PIPE>
__global__ void __launch_bounds__(TW*TH/2, MINB)
convlstm2(const float* __restrict__ xin,
          const float* __restrict__ hin,
          const float* __restrict__ cin,
          const float* __restrict__ w,
          const float* __restrict__ bias,
          float* __restrict__ hout,
          float* __restrict__ cout,
          const float* __restrict__ rand_mask,
          const int*   __restrict__ samples,
          float* __restrict__ fovea,
          float* __restrict__ hr)
{
    constexpr int CIN    = CX + CH;
    constexpr int HALO_W = TW + 2;
    constexpr int HALO_H = TH + 2;
    constexpr int TSZ    = HALO_H * HALO_W;
    constexpr int NT     = TW * TH / 2;
    constexpr int WSTG   = STAGE_W ? (4 * CHB * CIN * 9) : (4 * CH * CIN * 9);

    extern __shared__ float smem[];
    float* s_in = smem;                 // CIN * TSZ
    float* s_w  = smem + CIN * TSZ;     // WSTG, reordered [c][ci][tap][gate]

    const int tid = threadIdx.x;
    const int tx  = tid % TW;
    const int tyy = tid / TW;           // 0..TH/2-1
    const int x0  = blockIdx.x * TW;
    const int y0  = blockIdx.y * TH;
    const int b   = blockIdx.z;

    int px32 = 0, py32 = 0;
    if (FUSE_MASK) {
        int s = samples[b];
        px32 = (s / 7) * 32;
        py32 = (s - (s / 7) * 7) * 32;
    }

    // ---- input halo tiles (ONCE per block), simple strided fill ----
    for (int ci = 0; ci < CIN; ci++) {
        const float* src = (ci < CX)
            ? xin + ((size_t)b*CX + ci)      * HW
            : hin + ((size_t)b*CH + (ci-CX)) * HW;
        float* dst = s_in + ci * TSZ;
        for (int i = tid; i < TSZ; i += NT) {
            int yy = i / HALO_W;
            int xx = i - yy * HALO_W;
            int gy = y0 + yy - 1;
            int gx = x0 + xx - 1;
            float v = 0.0f;
            if (gy >= 0 && gy < NN && gx >= 0 && gx < NN) {
                float xv = src[gy * NN + gx];
                if (FUSE_MASK && ci < CX) {
                    bool patch = (gy >= px32) && (gy < px32 + 32) &&
                                 (gx >= py32) && (gx < py32 + 32);
                    float rm = rand_mask[(size_t)b*HW + gy*NN + gx];
                    bool m = (rm > 0.95f) || patch;
                    float vm = m ? xv : 0.0f;
                    v = vm;
                    if (yy >= 1 && yy <= TH && xx >= 1 && xx <= TW) {
                        size_t o = ((size_t)b*CX + ci)*HW + (size_t)gy*NN + gx;
                        fovea[o] = vm;
                        hr[o]    = patch ? xv : 0.0f;
                    }
                } else {
                    v = xv;
                }
            }
            dst[i] = v;
        }
    }
    // ---- resident weights (non-staged) ----
    if (!STAGE_W) {
        for (int s = tid; s < 4*CH*CIN*9; s += NT) {
            int g    = s & 3;
            int t    = (s >> 2) % 9;
            int rest = (s >> 2) / 9;    // ch*CIN + ci
            int ci   = rest % CIN;
            int ch   = rest / CIN;
            s_w[s] = w[((g*CH + ch)*CIN + ci)*9 + t];
        }
    }
    __syncthreads();

    const int r0 = tyy * 2;

    for (int chb = 0; chb < CH; chb += CHB) {
        if (STAGE_W) {
            __syncthreads();            // protect previous iteration's reads
            for (int s = tid; s < WSTG; s += NT) {
                int g    = s & 3;
                int t    = (s >> 2) % 9;
                int rest = (s >> 2) / 9;  // c*CIN + ci
                int ci   = rest % CIN;
                int c    = rest / CIN;    // 0..CHB-1
                s_w[s] = w[((g*CH + chb + c)*CIN + ci)*9 + t];
            }
            __syncthreads();
        }

        ull acc_if[CHB][2], acc_og[CHB][2];
#pragma unroll
        for (int c = 0; c < CHB; c++) {
            int ch = chb + c;
            ull bif = pack2(bias[ch],        bias[CH + ch]);
            ull bog = pack2(bias[2*CH + ch], bias[3*CH + ch]);
#pragma unroll
            for (int p = 0; p < 2; p++) { acc_if[c][p] = bif; acc_og[c][p] = bog; }
        }

        auto load_vd = [&](ull (&vd)[4][3], int ci) {
            const float* tile = s_in + ci * TSZ + r0 * HALO_W + tx;
#pragma unroll
            for (int k = 0; k < 4; k++)
#pragma unroll
                for (int dx = 0; dx < 3; dx++) {
                    float v = tile[k*HALO_W + dx];
                    vd[k][dx] = pack2(v, v);
                }
        };
        auto do_ffma = [&](ull (&vd)[4][3], int ci) {
#pragma unroll
            for (int c = 0; c < CHB; c++) {
                // one LDS.128 per tap: (wi,wf) in .x, (wo,wg) in .y
                const ulonglong2* wp = STAGE_W
                    ? (const ulonglong2*)(s_w + (c*CIN + ci) * 36)
                    : (const ulonglong2*)(s_w + ((chb + c)*CIN + ci) * 36);
#pragma unroll
                for (int dy = 0; dy < 3; dy++)
#pragma unroll
                    for (int dx = 0; dx < 3; dx++) {
                        ulonglong2 wv = wp[dy*3 + dx];
#pragma unroll
                        for (int p = 0; p < 2; p++) {
                            acc_if[c][p] = fma2(vd[p + dy][dx], wv.x, acc_if[c][p]);
                            acc_og[c][p] = fma2(vd[p + dy][dx], wv.y, acc_og[c][p]);
                        }
                    }
            }
        };

        if (PIPE) {
            // ping-pong: LDS for ci+1 issue before FFMA block of ci
            ull vdA[4][3], vdB[4][3];
            load_vd(vdA, 0);
            for (int ci = 0; ci + 2 <= CIN; ci += 2) {
                load_vd(vdB, ci + 1);
                do_ffma(vdA, ci);
                if (ci + 2 < CIN) load_vd(vdA, ci + 2);
                do_ffma(vdB, ci + 1);
            }
            if (CIN & 1) do_ffma(vdA, CIN - 1);
        } else {
            for (int ci = 0; ci < CIN; ci++) {
                ull vd[4][3];
                load_vd(vd, ci);
                do_ffma(vd, ci);
            }
        }

        // epilogue: gating + activations (HW tanh)
#pragma unroll
        for (int c = 0; c < CHB; c++) {
            int ch = chb + c;
#pragma unroll
            for (int p = 0; p < 2; p++) {
                float zi, zf, zo, zg;
                unpack2(acc_if[c][p], zi, zf);
                unpack2(acc_og[c][p], zo, zg);
                int y = y0 + r0 + p;
                size_t gidx = ((size_t)b*CH + ch)*HW + (size_t)y*NN + x0 + tx;
                float ig = fast_sig(zi);
                float fg = fast_sig(zf);
                float og = fast_sig(zo);
                float gg = hw_tanh(zg);
                float cp = cin[gidx];
                float cn = fg * cp + ig * gg;
                cout[gidx] = cn;
                hout[gidx] = og * hw_tanh(cn);
            }
        }
    }
}

// ---------------------------------------------------------------------------
// Reconstruction conv (3->3, 3x3) + hidden = h3n copy  (untouched)
// ---------------------------------------------------------------------------
__global__ void __launch_bounds__(256, 4)
recon_kernel(const float* __restrict__ h3,
             const float* __restrict__ wc,
             const float* __restrict__ bc,
             float* __restrict__ recon,
             float* __restrict__ hidden)
{
    __shared__ float s_in[3 * 34 * 34];
    __shared__ float s_w[3 * 3 * 9];
    __shared__ float s_b[3];

    const int tx  = threadIdx.x;
    const int ty  = threadIdx.y;
    const int tid = ty * 32 + tx;
    const int x0  = blockIdx.x * 32;
    const int y0  = blockIdx.y * 32;
    const int b   = blockIdx.z;

    for (int ci = 0; ci < 3; ci++) {
        const float* src = h3 + ((size_t)b*3 + ci) * HW;
        float* dst = s_in + ci * 1156;
        for (int i = tid; i < 1156; i += 256) {
            int yy = i / 34;
            int xx = i - yy * 34;
            int gy = y0 + yy - 1;
            int gx = x0 + xx - 1;
            float v = 0.0f;
            if (gy >= 0 && gy < NN && gx >= 0 && gx < NN)
                v = src[gy * NN + gx];
            dst[i] = v;
        }
    }
    if (tid < 81) s_w[tid] = wc[tid];
    if (tid < 3)  s_b[tid] = bc[tid];
    __syncthreads();

    for (int co = 0; co < 3; co++) {
        float acc[4];
#pragma unroll
        for (int p = 0; p < 4; p++) acc[p] = s_b[co];
        for (int ci = 0; ci < 3; ci++) {
            const float* tile = s_in + ci * 1156;
            const float* wp   = s_w + (co*3 + ci) * 9;
#pragma unroll
            for (int dy = 0; dy < 3; dy++)
#pragma unroll
                for (int dx = 0; dx < 3; dx++) {
                    float wv = wp[dy*3 + dx];
#pragma unroll
                    for (int p = 0; p < 4; p++) {
                        float v = tile[(ty + p*8 + dy)*34 + tx + dx];
                        acc[p] += v * wv;
                    }
                }
        }
#pragma unroll
        for (int p = 0; p < 4; p++) {
            int y = y0 + ty + p*8;
            size_t gidx = ((size_t)b*3 + co)*HW + (size_t)y*NN + x0 + tx;
            recon[gidx]  = acc[p];
            hidden[gidx] = s_in[co*1156 + (ty + p*8 + 1)*34 + tx + 1];
        }
    }
}

// ---------------------------------------------------------------------------
extern "C" void kernel_launch(void* const* d_in, const int* in_sizes, int n_in,
                              void* d_out, int out_size)
{
    const float* x         = (const float*)d_in[0];
    const float* h1        = (const float*)d_in[2];
    const float* c1        = (const float*)d_in[3];
    const float* h2        = (const float*)d_in[4];
    const float* c2        = (const float*)d_in[5];
    const float* h3        = (const float*)d_in[6];
    const float* c3        = (const float*)d_in[7];
    const float* rand_mask = (const float*)d_in[8];
    const int*   samples   = (const int*)  d_in[9];
    const float* w1        = (const float*)d_in[10];
    const float* b1        = (const float*)d_in[11];
    const float* w2        = (const float*)d_in[12];
    const float* b2        = (const float*)d_in[13];
    const float* w3        = (const float*)d_in[14];
    const float* b3        = (const float*)d_in[15];
    const float* wc        = (const float*)d_in[16];
    const float* bc        = (const float*)d_in[17];
    float* out = (float*)d_out;

    // conv1: fused mask, full weights resident.  PIPE + MINB=3.
    const int smem1 = (11*18*34 + 4*8*11*9) * 4;   // 39,600 B
    // conv2: staged weights (CHB=4), R11 form (MINB=3, no PIPE).
    const int smem2 = (24*18*34 + 4*4*24*9) * 4;   // 72,576 B -> 3 blocks/SM
    // conv3: full weights resident.  PIPE + MINB=3.
    const int smem3 = (19*18*34 + 4*3*19*9) * 4;   // 54,720 B

    auto k1 = convlstm2<3, 8, 4, 32, 16, 3, true,  false, true >;
    auto k2 = convlstm2<8, 16, 4, 32, 16, 3, false, true,  false>;
    auto k3 = convlstm2<16, 3, 3, 32, 16, 3, false, false, true >;

    cudaFuncSetAttribute((const void*)k1,
        cudaFuncAttributeMaxDynamicSharedMemorySize, smem1);
    cudaFuncSetAttribute((const void*)k2,
        cudaFuncAttributeMaxDynamicSharedMemorySize, smem2);
    cudaFuncSetAttribute((const void*)k3,
        cudaFuncAttributeMaxDynamicSharedMemorySize, smem3);

    dim3 grid(NN/32, NN/16, BATCH);    // (7, 14, 32)

    // 1) ConvLSTM 1 (fused mask): in = r_t0(3) + h1(8) -> h1n, c1n, fovea, hr
    k1<<<grid, 256, smem1>>>(
        x, h1, c1, w1, b1, out + OFF_H1, out + OFF_C1,
        rand_mask, samples, out + OFF_FOVEA, out + OFF_HR);

    // 2) ConvLSTM 2: in = h1n(8) + h2(16) -> h2n, c2n
    k2<<<grid, 256, smem2>>>(
        out + OFF_H1, h2, c2, w2, b2, out + OFF_H2, out + OFF_C2,
        nullptr, nullptr, nullptr, nullptr);

    // 3) ConvLSTM 3: in = h2n(16) + h3(3) -> h3n, c3n
    k3<<<grid, 256, smem3>>>(
        out + OFF_H2, h3, c3, w3, b3, out + OFF_H3, out + OFF_C3,
        nullptr, nullptr, nullptr, nullptr);

    // 4) reconstruction + hidden copy
    recon_kernel<<<dim3(7,7,BATCH), dim3(32,8)>>>(
        out + OFF_H3, wc, bc, out + OFF_RECON, out + OFF_HIDDEN);
}

// round 14
// speedup vs baseline: 1.0669x; 1.0669x over previous
#include <cuda_runtime.h>
#include <math.h>

#define NN 224
#define HW (NN*NN)
#define BATCH 32

typedef unsigned long long ull;

// d_out offsets (floats), in reference return order:
// h1n, c1n, h2n, c2n, h3n, c3n, reconstruction, fovea, hr, hidden
#define SZ8  ((size_t)BATCH*8*HW)
#define SZ16 ((size_t)BATCH*16*HW)
#define SZ3  ((size_t)BATCH*3*HW)
#define OFF_H1     ((size_t)0)
#define OFF_C1     (OFF_H1 + SZ8)
#define OFF_H2     (OFF_C1 + SZ8)
#define OFF_C2     (OFF_H2 + SZ16)
#define OFF_H3     (OFF_C2 + SZ16)
#define OFF_C3     (OFF_H3 + SZ3)
#define OFF_RECON  (OFF_C3 + SZ3)
#define OFF_FOVEA  (OFF_RECON + SZ3)
#define OFF_HR     (OFF_FOVEA + SZ3)
#define OFF_HIDDEN (OFF_HR + SZ3)

// HW tanh (sm_75+): single MUFU.TANH, max err ~1e-5 — far under 1e-3 budget
__device__ __forceinline__ float hw_tanh(float x) {
    float y;
    asm("tanh.approx.f32 %0, %1;" : "=f"(y) : "f"(x));
    return y;
}
// sigmoid via HW tanh: sigma(x) = 0.5 + 0.5*tanh(0.5x)  (3 instr)
__device__ __forceinline__ float fast_sig(float x) {
    return fmaf(hw_tanh(0.5f * x), 0.5f, 0.5f);
}

// ---- packed f32x2 helpers (sm_103a) --------------------------------------
__device__ __forceinline__ ull pack2(float lo, float hi) {
    ull r;
    asm("mov.b64 %0, {%1, %2};" : "=l"(r) : "f"(lo), "f"(hi));
    return r;
}
__device__ __forceinline__ void unpack2(ull v, float& lo, float& hi) {
    asm("mov.b64 {%0, %1}, %2;" : "=f"(lo), "=f"(hi) : "l"(v));
}
__device__ __forceinline__ ull fma2(ull a, ull b, ull c) {
    ull d;
    asm("fma.rn.f32x2 %0, %1, %2, %3;" : "=l"(d) : "l"(a), "l"(b), "l"(c));
    return d;
}

// ---------------------------------------------------------------------------
// Fused ConvLSTM step, f32x2 packed gate-pairs.  (R11 baseline + PRE_CIN)
// TW x TH output tile, TW*TH/2 threads; thread handles col tx, 2 rows.
// smem: CIN halo tiles ((TH+2) x (TW+2)) + weights [ch][ci][tap][gate]
// so ONE LDS.128 per tap yields both packed (w_i,w_f) and (w_o,w_g).
// STAGE_W: stage only CHB channels of weights per outer iteration (conv2) —
// input halo is loaded ONCE per block.
// PRE_CIN (this round's isolated change): issue the CHB*2 cell-state LDGs
// BEFORE the ci FFMA loop — their ~600-cycle latency overlaps ~3000 cycles
// of compute instead of being exposed in the epilogue.
// FUSE_MASK: layer-1 computes r_t0 = x*mask inline and emits fovea/hr.
// ---------------------------------------------------------------------------
template<int CX, int CH, int CHB, int TW, int TH, int MINB,
         bool FUSE_MASK, bool STAGE_W>
__global__ void __launch_bounds__(TW*TH/2, MINB)
convlstm2(const float* __restrict__ xin,
          const float* __restrict__ hin,
          const float* __restrict__ cin,
          const float* __restrict__ w,
          const float* __restrict__ bias,
          float* __restrict__ hout,
          float* __restrict__ cout,
          const float* __restrict__ rand_mask,
          const int*   __restrict__ samples,
          float* __restrict__ fovea,
          float* __restrict__ hr)
{
    constexpr int CIN    = CX + CH;
    constexpr int HALO_W = TW + 2;
    constexpr int HALO_H = TH + 2;
    constexpr int TSZ    = HALO_H * HALO_W;
    constexpr int NT     = TW * TH / 2;
    constexpr int WSTG   = STAGE_W ? (4 * CHB * CIN * 9) : (4 * CH * CIN * 9);

    extern __shared__ float smem[];
    float* s_in = smem;                 // CIN * TSZ
    float* s_w  = smem + CIN * TSZ;     // WSTG, reordered [c][ci][tap][gate]

    const int tid = threadIdx.x;
    const int tx  = tid % TW;
    const int tyy = tid / TW;           // 0..TH/2-1
    const int x0  = blockIdx.x * TW;
    const int y0  = blockIdx.y * TH;
    const int b   = blockIdx.z;

    int px32 = 0, py32 = 0;
    if (FUSE_MASK) {
        int s = samples[b];
        px32 = (s / 7) * 32;
        py32 = (s - (s / 7) * 7) * 32;
    }

    // ---- input halo tiles (ONCE per block), simple strided fill ----
    for (int ci = 0; ci < CIN; ci++) {
        const float* src = (ci < CX)
            ? xin + ((size_t)b*CX + ci)      * HW
            : hin + ((size_t)b*CH + (ci-CX)) * HW;
        float* dst = s_in + ci * TSZ;
        for (int i = tid; i < TSZ; i += NT) {
            int yy = i / HALO_W;
            int xx = i - yy * HALO_W;
            int gy = y0 + yy - 1;
            int gx = x0 + xx - 1;
            float v = 0.0f;
            if (gy >= 0 && gy < NN && gx >= 0 && gx < NN) {
                float xv = src[gy * NN + gx];
                if (FUSE_MASK && ci < CX) {
                    bool patch = (gy >= px32) && (gy < px32 + 32) &&
                                 (gx >= py32) && (gx < py32 + 32);
                    float rm = rand_mask[(size_t)b*HW + gy*NN + gx];
                    bool m = (rm > 0.95f) || patch;
                    float vm = m ? xv : 0.0f;
                    v = vm;
                    if (yy >= 1 && yy <= TH && xx >= 1 && xx <= TW) {
                        size_t o = ((size_t)b*CX + ci)*HW + (size_t)gy*NN + gx;
                        fovea[o] = vm;
                        hr[o]    = patch ? xv : 0.0f;
                    }
                } else {
                    v = xv;
                }
            }
            dst[i] = v;
        }
    }
    // ---- resident weights (non-staged) ----
    if (!STAGE_W) {
        for (int s = tid; s < 4*CH*CIN*9; s += NT) {
            int g    = s & 3;
            int t    = (s >> 2) % 9;
            int rest = (s >> 2) / 9;    // ch*CIN + ci
            int ci   = rest % CIN;
            int ch   = rest / CIN;
            s_w[s] = w[((g*CH + ch)*CIN + ci)*9 + t];
        }
    }
    __syncthreads();

    const int r0 = tyy * 2;

    for (int chb = 0; chb < CH; chb += CHB) {
        if (STAGE_W) {
            __syncthreads();            // protect previous iteration's reads
            for (int s = tid; s < WSTG; s += NT) {
                int g    = s & 3;
                int t    = (s >> 2) % 9;
                int rest = (s >> 2) / 9;  // c*CIN + ci
                int ci   = rest % CIN;
                int c    = rest / CIN;    // 0..CHB-1
                s_w[s] = w[((g*CH + chb + c)*CIN + ci)*9 + t];
            }
            __syncthreads();
        }

        // PRE_CIN: batch the cell-state LDGs up-front; latency hides
        // behind the ci FFMA loop below.
        float cpre[CHB][2];
        {
            size_t base = ((size_t)b*CH + chb)*HW
                        + (size_t)(y0 + r0)*NN + x0 + tx;
#pragma unroll
            for (int c = 0; c < CHB; c++)
#pragma unroll
                for (int p = 0; p < 2; p++)
                    cpre[c][p] = __ldg(cin + base + (size_t)c*HW + p*NN);
        }

        ull acc_if[CHB][2], acc_og[CHB][2];
#pragma unroll
        for (int c = 0; c < CHB; c++) {
            int ch = chb + c;
            ull bif = pack2(bias[ch],        bias[CH + ch]);
            ull bog = pack2(bias[2*CH + ch], bias[3*CH + ch]);
#pragma unroll
            for (int p = 0; p < 2; p++) { acc_if[c][p] = bif; acc_og[c][p] = bog; }
        }

        for (int ci = 0; ci < CIN; ci++) {
            const float* tile = s_in + ci * TSZ + r0 * HALO_W + tx;
            ull vd[4][3];
#pragma unroll
            for (int k = 0; k < 4; k++)
#pragma unroll
                for (int dx = 0; dx < 3; dx++) {
                    float v = tile[k*HALO_W + dx];
                    vd[k][dx] = pack2(v, v);
                }
#pragma unroll
            for (int c = 0; c < CHB; c++) {
                // one LDS.128 per tap: (wi,wf) in .x, (wo,wg) in .y
                const ulonglong2* wp = STAGE_W
                    ? (const ulonglong2*)(s_w + (c*CIN + ci) * 36)
                    : (const ulonglong2*)(s_w + ((chb + c)*CIN + ci) * 36);
#pragma unroll
                for (int dy = 0; dy < 3; dy++)
#pragma unroll
                    for (int dx = 0; dx < 3; dx++) {
                        ulonglong2 wv = wp[dy*3 + dx];
#pragma unroll
                        for (int p = 0; p < 2; p++) {
                            acc_if[c][p] = fma2(vd[p + dy][dx], wv.x, acc_if[c][p]);
                            acc_og[c][p] = fma2(vd[p + dy][dx], wv.y, acc_og[c][p]);
                        }
                    }
            }
        }

        // epilogue: gating + activations (HW tanh); cin already in regs
#pragma unroll
        for (int c = 0; c < CHB; c++) {
            int ch = chb + c;
#pragma unroll
            for (int p = 0; p < 2; p++) {
                float zi, zf, zo, zg;
                unpack2(acc_if[c][p], zi, zf);
                unpack2(acc_og[c][p], zo, zg);
                int y = y0 + r0 + p;
                size_t gidx = ((size_t)b*CH + ch)*HW + (size_t)y*NN + x0 + tx;
                float ig = fast_sig(zi);
                float fg = fast_sig(zf);
                float og = fast_sig(zo);
                float gg = hw_tanh(zg);
                float cn = fg * cpre[c][p] + ig * gg;
                cout[gidx] = cn;
                hout[gidx] = og * hw_tanh(cn);
            }
        }
    }
}

// ---------------------------------------------------------------------------
// Reconstruction conv (3->3, 3x3) + hidden = h3n copy  (untouched)
// ---------------------------------------------------------------------------
__global__ void __launch_bounds__(256, 4)
recon_kernel(const float* __restrict__ h3,
             const float* __restrict__ wc,
             const float* __restrict__ bc,
             float* __restrict__ recon,
             float* __restrict__ hidden)
{
    __shared__ float s_in[3 * 34 * 34];
    __shared__ float s_w[3 * 3 * 9];
    __shared__ float s_b[3];

    const int tx  = threadIdx.x;
    const int ty  = threadIdx.y;
    const int tid = ty * 32 + tx;
    const int x0  = blockIdx.x * 32;
    const int y0  = blockIdx.y * 32;
    const int b   = blockIdx.z;

    for (int ci = 0; ci < 3; ci++) {
        const float* src = h3 + ((size_t)b*3 + ci) * HW;
        float* dst = s_in + ci * 1156;
        for (int i = tid; i < 1156; i += 256) {
            int yy = i / 34;
            int xx = i - yy * 34;
            int gy = y0 + yy - 1;
            int gx = x0 + xx - 1;
            float v = 0.0f;
            if (gy >= 0 && gy < NN && gx >= 0 && gx < NN)
                v = src[gy * NN + gx];
            dst[i] = v;
        }
    }
    if (tid < 81) s_w[tid] = wc[tid];
    if (tid < 3)  s_b[tid] = bc[tid];
    __syncthreads();

    for (int co = 0; co < 3; co++) {
        float acc[4];
#pragma unroll
        for (int p = 0; p < 4; p++) acc[p] = s_b[co];
        for (int ci = 0; ci < 3; ci++) {
            const float* tile = s_in + ci * 1156;
            const float* wp   = s_w + (co*3 + ci) * 9;
#pragma unroll
            for (int dy = 0; dy < 3; dy++)
#pragma unroll
                for (int dx = 0; dx < 3; dx++) {
                    float wv = wp[dy*3 + dx];
#pragma unroll
                    for (int p = 0; p < 4; p++) {
                        float v = tile[(ty + p*8 + dy)*34 + tx + dx];
                        acc[p] += v * wv;
                    }
                }
        }
#pragma unroll
        for (int p = 0; p < 4; p++) {
            int y = y0 + ty + p*8;
            size_t gidx = ((size_t)b*3 + co)*HW + (size_t)y*NN + x0 + tx;
            recon[gidx]  = acc[p];
            hidden[gidx] = s_in[co*1156 + (ty + p*8 + 1)*34 + tx + 1];
        }
    }
}

// ---------------------------------------------------------------------------
extern "C" void kernel_launch(void* const* d_in, const int* in_sizes, int n_in,
                              void* d_out, int out_size)
{
    const float* x         = (const float*)d_in[0];
    const float* h1        = (const float*)d_in[2];
    const float* c1        = (const float*)d_in[3];
    const float* h2        = (const float*)d_in[4];
    const float* c2        = (const float*)d_in[5];
    const float* h3        = (const float*)d_in[6];
    const float* c3        = (const float*)d_in[7];
    const float* rand_mask = (const float*)d_in[8];
    const int*   samples   = (const int*)  d_in[9];
    const float* w1        = (const float*)d_in[10];
    const float* b1        = (const float*)d_in[11];
    const float* w2        = (const float*)d_in[12];
    const float* b2        = (const float*)d_in[13];
    const float* w3        = (const float*)d_in[14];
    const float* b3        = (const float*)d_in[15];
    const float* wc        = (const float*)d_in[16];
    const float* bc        = (const float*)d_in[17];
    float* out = (float*)d_out;

    // conv1: fused mask, full weights resident.  MINB=4 (R11).
    const int smem1 = (11*18*34 + 4*8*11*9) * 4;   // 39,600 B -> 4 blocks/SM
    // conv2: staged weights (CHB=4), input halo loaded once. MINB=3 (R11).
    const int smem2 = (24*18*34 + 4*4*24*9) * 4;   // 72,576 B -> 3 blocks/SM
    // conv3: full weights resident.  MINB=4 (R11).
    const int smem3 = (19*18*34 + 4*3*19*9) * 4;   // 54,720 B -> 4 blocks/SM

    auto k1 = convlstm2<3, 8, 4, 32, 16, 4, true,  false>;
    auto k2 = convlstm2<8, 16, 4, 32, 16, 3, false, true >;
    auto k3 = convlstm2<16, 3, 3, 32, 16, 4, false, false>;

    cudaFuncSetAttribute((const void*)k1,
        cudaFuncAttributeMaxDynamicSharedMemorySize, smem1);
    cudaFuncSetAttribute((const void*)k2,
        cudaFuncAttributeMaxDynamicSharedMemorySize, smem2);
    cudaFuncSetAttribute((const void*)k3,
        cudaFuncAttributeMaxDynamicSharedMemorySize, smem3);

    dim3 grid(NN/32, NN/16, BATCH);    // (7, 14, 32)

    // 1) ConvLSTM 1 (fused mask): in = r_t0(3) + h1(8) -> h1n, c1n, fovea, hr
    k1<<<grid, 256, smem1>>>(
        x, h1, c1, w1, b1, out + OFF_H1, out + OFF_C1,
        rand_mask, samples, out + OFF_FOVEA, out + OFF_HR);

    // 2) ConvLSTM 2: in = h1n(8) + h2(16) -> h2n, c2n
    k2<<<grid, 256, smem2>>>(
        out + OFF_H1, h2, c2, w2, b2, out + OFF_H2, out + OFF_C2,
        nullptr, nullptr, nullptr, nullptr);

    // 3) ConvLSTM 3: in = h2n(16) + h3(3) -> h3n, c3n
    k3<<<grid, 256, smem3>>>(
        out + OFF_H2, h3, c3, w3, b3, out + OFF_H3, out + OFF_C3,
        nullptr, nullptr, nullptr, nullptr);

    // 4) reconstruction + hidden copy
    recon_kernel<<<dim3(7,7,BATCH), dim3(32,8)>>>(
        out + OFF_H3, wc, bc, out + OFF_RECON, out + OFF_HIDDEN);
}